// round 11
// baseline (speedup 1.0000x reference)
#include <cuda_runtime.h>
#include <cuda_bf16.h>
#include <cstdint>

typedef unsigned int u32;
typedef unsigned long long u64;

#define BB   8
#define CIN  512
#define MIDC 128
#define NNE  2304
#define SCALE_S 0.08838834764831845f
#define SCALE_E 0.125f            // E' = E/8 stored in e4m3
#define INV_OSCALE (1.0f/2048.0f) // 1/(8 * 16384/65536)... = 1/(SCALE_E*16384)

// ---------------- scratch layout (bytes) ----------------
#define XT_SZ   ((size_t)3*BB*NNE*CIN*2)
#define FT_ONE  ((size_t)BB*NNE*MIDC*2)
#define G_SZ    ((size_t)2*BB*MIDC*NNE*4)
#define GN_SZ   ((size_t)2*BB*MIDC*NNE*2)   // fp8 uses half of this
#define ET_SZ   ((size_t)2*BB*NNE*NNE*2)    // fp8 uses half of this
#define Z_SZ    ((size_t)2*BB*NNE*4)
#define OT_SZ   ((size_t)2*BB*NNE*MIDC*2)
#define WC_SZ   ((size_t)6*65536*2)

#define XT_OFF  0ull
#define FT_OFF  (XT_OFF + XT_SZ)
#define G_OFF   (FT_OFF + 3*FT_ONE)
#define GN_OFF  (G_OFF + G_SZ)
#define ET_OFF  (GN_OFF + GN_SZ)
#define Z_OFF   (ET_OFF + ET_SZ)
#define OT_OFF  (Z_OFF + Z_SZ)
#define WC_OFF  (OT_OFF + OT_SZ)
#define TOTAL_SCRATCH (WC_OFF + WC_SZ)

__device__ __align__(1024) char d_scratch[TOTAL_SCRATCH];

// ---------------- MMA building blocks ----------------
__device__ __forceinline__ u32 pack_bf16(float lo, float hi) {
    u32 r; asm("cvt.rn.bf16x2.f32 %0, %1, %2;" : "=r"(r) : "f"(hi), "f"(lo)); return r;
}
__device__ __forceinline__ unsigned short pack_e4m3(float lo, float hi) {
    unsigned short r;
    asm("cvt.rn.satfinite.e4m3x2.f32 %0, %1, %2;" : "=h"(r) : "f"(hi), "f"(lo));
    return r;
}
__device__ __forceinline__ void cpasync16(u32 saddr, const void* g) {
    asm volatile("cp.async.cg.shared.global [%0], [%1], 16;" :: "r"(saddr), "l"(g));
}
#define CP_COMMIT() asm volatile("cp.async.commit_group;" ::: "memory")

__device__ __forceinline__ void ldsm_x4(u32 a, u32& r0, u32& r1, u32& r2, u32& r3) {
    asm volatile("ldmatrix.sync.aligned.m8n8.x4.shared.b16 {%0,%1,%2,%3}, [%4];"
                 : "=r"(r0), "=r"(r1), "=r"(r2), "=r"(r3) : "r"(a));
}
__device__ __forceinline__ void mma16816(float c[4], const u32 a[4], u32 b0, u32 b1) {
    asm volatile("mma.sync.aligned.m16n8k16.row.col.f32.bf16.bf16.f32 "
                 "{%0,%1,%2,%3}, {%4,%5,%6,%7}, {%8,%9}, {%0,%1,%2,%3};"
                 : "+f"(c[0]), "+f"(c[1]), "+f"(c[2]), "+f"(c[3])
                 : "r"(a[0]), "r"(a[1]), "r"(a[2]), "r"(a[3]), "r"(b0), "r"(b1));
}
__device__ __forceinline__ void mma16832_fp8(float c[4], const u32 a[4], u32 b0, u32 b1) {
    asm volatile("mma.sync.aligned.m16n8k32.row.col.f32.e4m3.e4m3.f32 "
                 "{%0,%1,%2,%3}, {%4,%5,%6,%7}, {%8,%9}, {%0,%1,%2,%3};"
                 : "+f"(c[0]), "+f"(c[1]), "+f"(c[2]), "+f"(c[3])
                 : "r"(a[0]), "r"(a[1]), "r"(a[2]), "r"(a[3]), "r"(b0), "r"(b1));
}

// Tile: 128 rows x 128 B (bf16: 64 elems; fp8: 128 elems). 8 x 16B chunks/row.
// Swizzle cc = c ^ (r&7) — conflict-free for cp.async stores and ldmatrix reads.
#define TILE_B 16384
#define NSTAGE 3

__device__ __forceinline__ u32 sw64(int r, int ch) {
    return (u32)(r * 128 + ((ch ^ (r & 7)) << 4));
}

// 256 threads: thread -> row tid>>1, 4 x 16B chunks. pitch/offset in BYTES.
__device__ __forceinline__ void tile_load(u32 sdst, const char* src,
                                          size_t pitchB, int k0B, int tid) {
    int r = tid >> 1;
    const char* g = src + (size_t)r * pitchB + k0B;
#pragma unroll
    for (int i = 0; i < 4; i++) {
        int c = (tid & 1) * 4 + i;
        cpasync16(sdst + sw64(r, c), g + c * 16);
    }
}

// CTA 128x128 bf16 GEMM: acc += A(128 x Kd) · B(128 x Kd)^T, k-major operands.
// 256 threads, 8 warps 2(M) x 4(N), warp tile 64x32, 3-stage cp.async pipeline.
__device__ __forceinline__ void hmma_gemm(
    u32 sA, u32 sB,
    const __nv_bfloat16* __restrict__ A, size_t pA,
    const __nv_bfloat16* __restrict__ B, size_t pB,
    int Kd, int tid, float acc[4][4][4])
{
#pragma unroll
    for (int i = 0; i < 4; i++)
#pragma unroll
        for (int j = 0; j < 4; j++)
#pragma unroll
            for (int e = 0; e < 4; e++) acc[i][j][e] = 0.f;

    const int lane = tid & 31, wid = tid >> 5;
    const int wm = wid & 1, wn = wid >> 1;
    const int T = Kd / 64;
    const char* Ab = (const char*)A;
    const char* Bb = (const char*)B;
    const size_t pAB = pA * 2, pBB = pB * 2;

    tile_load(sA, Ab, pAB, 0, tid);
    tile_load(sB, Bb, pBB, 0, tid);
    CP_COMMIT();
    if (T > 1) {
        tile_load(sA + TILE_B, Ab, pAB, 128, tid);
        tile_load(sB + TILE_B, Bb, pBB, 128, tid);
    }
    CP_COMMIT();

    int slot_next = 2 % NSTAGE;
    for (int t = 0; t < T; t++) {
        asm volatile("cp.async.wait_group 1;" ::: "memory");
        __syncthreads();
        if (t + 2 < T) {
            tile_load(sA + slot_next * TILE_B, Ab, pAB, (t + 2) * 128, tid);
            tile_load(sB + slot_next * TILE_B, Bb, pBB, (t + 2) * 128, tid);
        }
        CP_COMMIT();
        slot_next = (slot_next + 1 == NSTAGE) ? 0 : slot_next + 1;

        const int cur = t % NSTAGE;
        const u32 abuf = sA + cur * TILE_B;
        const u32 bbuf = sB + cur * TILE_B;
#pragma unroll
        for (int k16 = 0; k16 < 4; k16++) {
            u32 a[4][4];
#pragma unroll
            for (int f = 0; f < 4; f++) {
                int row = wm * 64 + f * 16 + (lane & 15);
                int ch  = k16 * 2 + (lane >> 4);
                ldsm_x4(abuf + sw64(row, ch), a[f][0], a[f][1], a[f][2], a[f][3]);
            }
            u32 b[4][2];
#pragma unroll
            for (int p = 0; p < 2; p++) {
                int row = wn * 32 + p * 16 + ((lane & 16) >> 1) + (lane & 7);
                int ch  = k16 * 2 + ((lane >> 3) & 1);
                ldsm_x4(bbuf + sw64(row, ch), b[2 * p][0], b[2 * p][1],
                        b[2 * p + 1][0], b[2 * p + 1][1]);
            }
#pragma unroll
            for (int mf = 0; mf < 4; mf++)
#pragma unroll
                for (int nf = 0; nf < 4; nf++)
                    mma16816(acc[mf][nf], a[mf], b[nf][0], b[nf][1]);
        }
    }
}

// CTA 128x128 FP8 GEMM: same structure, e4m3 operands, k32 steps, BK=128 fp8.
__device__ __forceinline__ void qmma_gemm(
    u32 sA, u32 sB,
    const char* __restrict__ A, size_t pAB,
    const char* __restrict__ B, size_t pBB,
    int KdB, int tid, float acc[4][4][4])
{
#pragma unroll
    for (int i = 0; i < 4; i++)
#pragma unroll
        for (int j = 0; j < 4; j++)
#pragma unroll
            for (int e = 0; e < 4; e++) acc[i][j][e] = 0.f;

    const int lane = tid & 31, wid = tid >> 5;
    const int wm = wid & 1, wn = wid >> 1;
    const int T = KdB / 128;

    tile_load(sA, A, pAB, 0, tid);
    tile_load(sB, B, pBB, 0, tid);
    CP_COMMIT();
    if (T > 1) {
        tile_load(sA + TILE_B, A, pAB, 128, tid);
        tile_load(sB + TILE_B, B, pBB, 128, tid);
    }
    CP_COMMIT();

    int slot_next = 2 % NSTAGE;
    for (int t = 0; t < T; t++) {
        asm volatile("cp.async.wait_group 1;" ::: "memory");
        __syncthreads();
        if (t + 2 < T) {
            tile_load(sA + slot_next * TILE_B, A, pAB, (t + 2) * 128, tid);
            tile_load(sB + slot_next * TILE_B, B, pBB, (t + 2) * 128, tid);
        }
        CP_COMMIT();
        slot_next = (slot_next + 1 == NSTAGE) ? 0 : slot_next + 1;

        const int cur = t % NSTAGE;
        const u32 abuf = sA + cur * TILE_B;
        const u32 bbuf = sB + cur * TILE_B;
#pragma unroll
        for (int k32 = 0; k32 < 4; k32++) {
            u32 a[4][4];
#pragma unroll
            for (int f = 0; f < 4; f++) {
                int row = wm * 64 + f * 16 + (lane & 15);
                int ch  = k32 * 2 + (lane >> 4);
                ldsm_x4(abuf + sw64(row, ch), a[f][0], a[f][1], a[f][2], a[f][3]);
            }
            u32 b[4][2];
#pragma unroll
            for (int p = 0; p < 2; p++) {
                int row = wn * 32 + p * 16 + ((lane & 16) >> 1) + (lane & 7);
                int ch  = k32 * 2 + ((lane >> 3) & 1);
                ldsm_x4(bbuf + sw64(row, ch), b[2 * p][0], b[2 * p][1],
                        b[2 * p + 1][0], b[2 * p + 1][1]);
            }
#pragma unroll
            for (int mf = 0; mf < 4; mf++)
#pragma unroll
                for (int nf = 0; nf < 4; nf++)
                    mma16832_fp8(acc[mf][nf], a[mf], b[nf][0], b[nf][1]);
        }
    }
}

#define SMEM_DYN (2 * NSTAGE * TILE_B)   // 96 KB

// ============================ SIMT prep ============================
__global__ __launch_bounds__(256) void transpose_x(
    const float* __restrict__ x, const float* __restrict__ x_v,
    const float* __restrict__ x_h, __nv_bfloat16* __restrict__ xT)
{
    __shared__ float t[32][33];
    int z = blockIdx.z, tt = z >> 3, b = z & 7;
    const float* src = (tt == 0) ? x : (tt == 1 ? x_v : x_h);
    int n0 = blockIdx.x * 32, c0 = blockIdx.y * 32;
    int tx = threadIdx.x & 31, ty8 = threadIdx.x >> 5;
#pragma unroll
    for (int i = 0; i < 4; i++)
        t[ty8 + i * 8][tx] = src[((size_t)b * CIN + c0 + ty8 + i * 8) * NNE + n0 + tx];
    __syncthreads();
#pragma unroll
    for (int i = 0; i < 4; i++)
        xT[(((size_t)tt * BB + b) * NNE + n0 + ty8 + i * 8) * CIN + c0 + tx] =
            __float2bfloat16(t[tx][ty8 + i * 8]);
}

struct WC6 { const float* s[6]; };
__global__ __launch_bounds__(256) void conv_weights(WC6 w, __nv_bfloat16* __restrict__ dst,
                                                    float* __restrict__ Z)
{
    int idx = blockIdx.x * 256 + threadIdx.x;
    int t = idx >> 16, i = idx & 65535;
    dst[(size_t)t * 65536 + i] = __float2bfloat16(w.s[t][i]);
    if (idx < 2 * BB * NNE) Z[idx] = 0.f;
}

// gn8[idx] = e4m3(g * 16384 / Z[n])  (2 elems/thread)
__global__ __launch_bounds__(256) void gnorm(
    const float* __restrict__ g, const float* __restrict__ Z,
    unsigned char* __restrict__ gn8)
{
    size_t idx = ((size_t)blockIdx.x * 256 + threadIdx.x) * 2;
    int n = (int)(idx % NNE);
    size_t sb = idx / ((size_t)NNE * MIDC);
    const float* zr = Z + sb * NNE;
    float v0 = g[idx]     * __frcp_rn(zr[n])     * 16384.f;
    float v1 = g[idx + 1] * __frcp_rn(zr[n + 1]) * 16384.f;
    *reinterpret_cast<unsigned short*>(gn8 + idx) = pack_e4m3(v0, v1);
}

// ============================ tensor kernels ============================

// f[o][b][n][m] = relu(BN(xT·W^T)). grid (18, BB, 3).
__global__ __launch_bounds__(256, 2) void k_fconv(
    const __nv_bfloat16* __restrict__ xT, const __nv_bfloat16* __restrict__ Wc,
    const float* __restrict__ ba, const float* __restrict__ ga, const float* __restrict__ ta,
    const float* __restrict__ bv, const float* __restrict__ gv, const float* __restrict__ tv,
    __nv_bfloat16* __restrict__ ft)
{
    extern __shared__ char dsm[];
    __shared__ float sS[128], sC[128];
    int tid = threadIdx.x, lane = tid & 31, wid = tid >> 5;
    int wm = wid & 1, wn = wid >> 1;
    int nt = blockIdx.x, b = blockIdx.y, o = blockIdx.z;

    if (tid < 128) {
        const float* bias  = (o == 0) ? ba : bv;
        const float* gamma = (o == 0) ? ga : gv;
        const float* beta  = (o == 0) ? ta : tv;
        float s = gamma[tid] * rsqrtf(1.f + 1e-5f);
        sS[tid] = s; sC[tid] = bias[tid] * s + beta[tid];
    }

    const __nv_bfloat16* A = xT + (((size_t)o * BB + b) * NNE + (size_t)nt * 128) * CIN;
    const __nv_bfloat16* B = Wc + (size_t)((o == 0) ? 0 : 1) * 65536;

    float acc[4][4][4];
    u32 sA = (u32)__cvta_generic_to_shared(dsm);
    u32 sB = sA + NSTAGE * TILE_B;
    hmma_gemm(sA, sB, A, CIN, B, CIN, CIN, tid, acc);

    __nv_bfloat16* dst = ft + (size_t)o * (size_t)BB * NNE * MIDC
                            + ((size_t)b * NNE + (size_t)nt * 128) * MIDC;
#pragma unroll
    for (int mf = 0; mf < 4; mf++)
#pragma unroll
        for (int nf = 0; nf < 4; nf++)
#pragma unroll
            for (int h = 0; h < 2; h++) {
                int r = wm * 64 + mf * 16 + (lane >> 2) + h * 8;
                int c = wn * 32 + nf * 8 + ((lane & 3) << 1);
                float y0 = fmaxf(acc[mf][nf][h * 2]     * sS[c]     + sC[c],     0.f);
                float y1 = fmaxf(acc[mf][nf][h * 2 + 1] * sS[c + 1] + sC[c + 1], 0.f);
                *reinterpret_cast<u32*>(dst + (size_t)r * MIDC + c) = pack_bf16(y0, y1);
            }
}

// g[sel][b][m][n] = Wg·xT^T + bias (fp32). grid (18, BB, 2).
__global__ __launch_bounds__(256, 2) void k_gconv(
    const __nv_bfloat16* __restrict__ xT, const __nv_bfloat16* __restrict__ Wc,
    const float* __restrict__ bgav, const float* __restrict__ bgah,
    float* __restrict__ g)
{
    extern __shared__ char dsm[];
    int tid = threadIdx.x, lane = tid & 31, wid = tid >> 5;
    int wm = wid & 1, wn = wid >> 1;
    int nt = blockIdx.x, b = blockIdx.y, o = blockIdx.z;

    const __nv_bfloat16* A = Wc + (size_t)(2 + o) * 65536;
    const __nv_bfloat16* B = xT + ((size_t)b * NNE + (size_t)nt * 128) * CIN;

    float acc[4][4][4];
    u32 sA = (u32)__cvta_generic_to_shared(dsm);
    u32 sB = sA + NSTAGE * TILE_B;
    hmma_gemm(sA, sB, A, CIN, B, CIN, CIN, tid, acc);

    const float* bias = (o == 0) ? bgav : bgah;
    float* dst = g + (size_t)(o * BB + b) * MIDC * NNE + (size_t)nt * 128;
#pragma unroll
    for (int mf = 0; mf < 4; mf++)
#pragma unroll
        for (int nf = 0; nf < 4; nf++)
#pragma unroll
            for (int h = 0; h < 2; h++) {
                int r = wm * 64 + mf * 16 + (lane >> 2) + h * 8;
                int c = wn * 32 + nf * 8 + ((lane & 3) << 1);
                float bval = bias[r];
                *reinterpret_cast<float2*>(dst + (size_t)r * NNE + c) =
                    make_float2(acc[mf][nf][h * 2] + bval, acc[mf][nf][h * 2 + 1] + bval);
            }
}

// ET8[sel][b][j][i] = e4m3(exp(scale*fa[j]·fq[i]) * SCALE_E); Z[sel][b][i] += col sums.
// grid (it 18, jt 18, b + 8*sel).
__global__ __launch_bounds__(256, 2) void k_score(
    const __nv_bfloat16* __restrict__ ft, unsigned char* __restrict__ et,
    float* __restrict__ Z)
{
    extern __shared__ char dsm[];
    __shared__ float zs[2][128];
    int tid = threadIdx.x, lane = tid & 31, wid = tid >> 5;
    int wm = wid & 1, wn = wid >> 1;
    int it = blockIdx.x, jt = blockIdx.y;
    int z = blockIdx.z, b = z & 7, sel = z >> 3;

    const __nv_bfloat16* fa = ft + (size_t)b * NNE * MIDC;
    const __nv_bfloat16* fq = ft + (size_t)(1 + sel) * (size_t)BB * NNE * MIDC
                                 + (size_t)b * NNE * MIDC;
    const __nv_bfloat16* A = fa + (size_t)jt * 128 * MIDC;
    const __nv_bfloat16* B = fq + (size_t)it * 128 * MIDC;

    float acc[4][4][4];
    u32 sA = (u32)__cvta_generic_to_shared(dsm);
    u32 sB = sA + NSTAGE * TILE_B;
    hmma_gemm(sA, sB, A, MIDC, B, MIDC, MIDC, tid, acc);

#pragma unroll
    for (int mf = 0; mf < 4; mf++)
#pragma unroll
        for (int nf = 0; nf < 4; nf++)
#pragma unroll
            for (int e = 0; e < 4; e++)
                acc[mf][nf][e] = __expf(acc[mf][nf][e] * SCALE_S);

    unsigned char* dst = et + ((size_t)(sel * BB + b) * NNE + (size_t)jt * 128) * NNE
                            + (size_t)it * 128;
#pragma unroll
    for (int mf = 0; mf < 4; mf++)
#pragma unroll
        for (int nf = 0; nf < 4; nf++)
#pragma unroll
            for (int h = 0; h < 2; h++) {
                int r = wm * 64 + mf * 16 + (lane >> 2) + h * 8;
                int c = wn * 32 + nf * 8 + ((lane & 3) << 1);
                *reinterpret_cast<unsigned short*>(dst + (size_t)r * NNE + c) =
                    pack_e4m3(acc[mf][nf][h * 2] * SCALE_E,
                              acc[mf][nf][h * 2 + 1] * SCALE_E);
            }

#pragma unroll
    for (int nf = 0; nf < 4; nf++) {
        float s0 = 0.f, s1 = 0.f;
#pragma unroll
        for (int mf = 0; mf < 4; mf++) {
            s0 += acc[mf][nf][0] + acc[mf][nf][2];
            s1 += acc[mf][nf][1] + acc[mf][nf][3];
        }
#pragma unroll
        for (int off = 4; off < 32; off <<= 1) {
            s0 += __shfl_xor_sync(0xffffffffu, s0, off);
            s1 += __shfl_xor_sync(0xffffffffu, s1, off);
        }
        if (lane < 4) {
            int c = wn * 32 + nf * 8 + lane * 2;
            zs[wm][c] = s0;
            zs[wm][c + 1] = s1;
        }
    }
    __syncthreads();
    if (tid < 128)
        atomicAdd(&Z[(size_t)(sel * BB + b) * NNE + (size_t)it * 128 + tid],
                  zs[0][tid] + zs[1][tid]);
}

// oT[sel][b][j][m] = (1/2048) * sum_i ET8[j][i]·gn8[m][i]  — FP8 GEMM.
// grid (jt 18, 1, b+8*sel).
__global__ __launch_bounds__(256, 2) void k_ogemm(
    const unsigned char* __restrict__ et, const unsigned char* __restrict__ gn8,
    __nv_bfloat16* __restrict__ oT)
{
    extern __shared__ char dsm[];
    int tid = threadIdx.x, lane = tid & 31, wid = tid >> 5;
    int wm = wid & 1, wn = wid >> 1;
    int jt = blockIdx.x;
    int z = blockIdx.z, b = z & 7, sel = z >> 3;

    const char* A = (const char*)et + ((size_t)(sel * BB + b) * NNE + (size_t)jt * 128) * NNE;
    const char* B = (const char*)gn8 + (size_t)(sel * BB + b) * MIDC * NNE;

    float acc[4][4][4];
    u32 sA = (u32)__cvta_generic_to_shared(dsm);
    u32 sB = sA + NSTAGE * TILE_B;
    qmma_gemm(sA, sB, A, NNE, B, NNE, NNE, tid, acc);

    __nv_bfloat16* dst = oT + ((size_t)(sel * BB + b) * NNE + (size_t)jt * 128) * MIDC;
#pragma unroll
    for (int mf = 0; mf < 4; mf++)
#pragma unroll
        for (int nf = 0; nf < 4; nf++)
#pragma unroll
            for (int h = 0; h < 2; h++) {
                int r = wm * 64 + mf * 16 + (lane >> 2) + h * 8;
                int c = wn * 32 + nf * 8 + ((lane & 3) << 1);
                *reinterpret_cast<u32*>(dst + (size_t)r * MIDC + c) =
                    pack_bf16(acc[mf][nf][h * 2] * INV_OSCALE,
                              acc[mf][nf][h * 2 + 1] * INV_OSCALE);
            }
}

// out[sel][b][cout][n] = Wf·oT^T + bias + x. grid (nt 18, ct 4, b+8*sel).
__global__ __launch_bounds__(256, 2) void k_outconv(
    const __nv_bfloat16* __restrict__ Wc, const __nv_bfloat16* __restrict__ oT,
    const float* __restrict__ bfav, const float* __restrict__ bfah,
    const float* __restrict__ x,
    float* __restrict__ out_v, float* __restrict__ out_h)
{
    extern __shared__ char dsm[];
    int tid = threadIdx.x, lane = tid & 31, wid = tid >> 5;
    int wm = wid & 1, wn = wid >> 1;
    int nt = blockIdx.x, ct = blockIdx.y;
    int z = blockIdx.z, b = z & 7, sel = z >> 3;

    const __nv_bfloat16* A = Wc + (size_t)(4 + sel) * 65536 + (size_t)ct * 128 * MIDC;
    const __nv_bfloat16* B = oT + ((size_t)(sel * BB + b) * NNE + (size_t)nt * 128) * MIDC;

    float acc[4][4][4];
    u32 sA = (u32)__cvta_generic_to_shared(dsm);
    u32 sB = sA + NSTAGE * TILE_B;
    hmma_gemm(sA, sB, A, MIDC, B, MIDC, MIDC, tid, acc);

    const float* bias = (sel == 0) ? bfav : bfah;
    float* outp = (sel == 0) ? out_v : out_h;
#pragma unroll
    for (int mf = 0; mf < 4; mf++)
#pragma unroll
        for (int nf = 0; nf < 4; nf++)
#pragma unroll
            for (int h = 0; h < 2; h++) {
                int r = wm * 64 + mf * 16 + (lane >> 2) + h * 8;
                int c = wn * 32 + nf * 8 + ((lane & 3) << 1);
                int cout = ct * 128 + r;
                size_t base = ((size_t)b * CIN + cout) * NNE + (size_t)nt * 128 + c;
                float2 xv = *reinterpret_cast<const float2*>(x + base);
                float bval = bias[cout];
                *reinterpret_cast<float2*>(outp + base) =
                    make_float2(acc[mf][nf][h * 2] + bval + xv.x,
                                acc[mf][nf][h * 2 + 1] + bval + xv.y);
            }
}

// ============================================================================
extern "C" void kernel_launch(void* const* d_in, const int* in_sizes, int n_in,
                              void* d_out, int out_size)
{
    (void)in_sizes; (void)n_in; (void)out_size;

    const float* x    = (const float*)d_in[0];
    const float* x_h  = (const float*)d_in[1];
    const float* x_v  = (const float*)d_in[2];
    const float* Wa   = (const float*)d_in[3];
    const float* ba   = (const float*)d_in[4];
    const float* ga   = (const float*)d_in[5];
    const float* ta   = (const float*)d_in[6];
    const float* Wv   = (const float*)d_in[7];
    const float* bv   = (const float*)d_in[8];
    const float* gv   = (const float*)d_in[9];
    const float* tv   = (const float*)d_in[10];
    const float* Wgav = (const float*)d_in[11];
    const float* bgav = (const float*)d_in[12];
    const float* Wgah = (const float*)d_in[13];
    const float* bgah = (const float*)d_in[14];
    const float* Wfav = (const float*)d_in[15];
    const float* bfav = (const float*)d_in[16];
    const float* Wfah = (const float*)d_in[17];
    const float* bfah = (const float*)d_in[18];

    void* sp = nullptr;
    cudaGetSymbolAddress(&sp, d_scratch);
    char* base = (char*)sp;
    __nv_bfloat16* xT  = (__nv_bfloat16*)(base + XT_OFF);
    __nv_bfloat16* ft  = (__nv_bfloat16*)(base + FT_OFF);
    float*         g   = (float*)(base + G_OFF);
    unsigned char* gn8 = (unsigned char*)(base + GN_OFF);
    unsigned char* et  = (unsigned char*)(base + ET_OFF);
    float*         Zp  = (float*)(base + Z_OFF);
    __nv_bfloat16* oT  = (__nv_bfloat16*)(base + OT_OFF);
    __nv_bfloat16* Wc  = (__nv_bfloat16*)(base + WC_OFF);

    float* out_h = (float*)d_out;
    float* out_v = out_h + (size_t)BB * CIN * NNE;

    static int attr_done = 0;
    if (!attr_done) {
        cudaFuncSetAttribute(k_fconv,   cudaFuncAttributeMaxDynamicSharedMemorySize, SMEM_DYN);
        cudaFuncSetAttribute(k_gconv,   cudaFuncAttributeMaxDynamicSharedMemorySize, SMEM_DYN);
        cudaFuncSetAttribute(k_score,   cudaFuncAttributeMaxDynamicSharedMemorySize, SMEM_DYN);
        cudaFuncSetAttribute(k_ogemm,   cudaFuncAttributeMaxDynamicSharedMemorySize, SMEM_DYN);
        cudaFuncSetAttribute(k_outconv, cudaFuncAttributeMaxDynamicSharedMemorySize, SMEM_DYN);
        attr_done = 1;
    }

    // prep: transpose x to bf16 [n][c]; weights to bf16; zero Z
    transpose_x<<<dim3(NNE / 32, CIN / 32, 3 * BB), 256>>>(x, x_v, x_h, xT);
    WC6 w = {{ Wa, Wv, Wgav, Wgah, Wfav, Wfah }};
    conv_weights<<<1536, 256>>>(w, Wc, Zp);

    // input convs
    k_fconv<<<dim3(18, BB, 3), 256, SMEM_DYN>>>(xT, Wc, ba, ga, ta, bv, gv, tv, ft);
    k_gconv<<<dim3(18, BB, 2), 256, SMEM_DYN>>>(xT, Wc, bgav, bgah, g);

    // scores: ET8 = e4m3(exp(scale*S)/8)^T, Z = per-query sums (fp32)
    k_score<<<dim3(18, 18, 16), 256, SMEM_DYN>>>(ft, et, Zp);

    // fold 16384/Z into g -> e4m3
    gnorm<<<(2 * BB * MIDC * NNE) / 512, 256>>>(g, Zp, gn8);

    // oT = (ET8 · gn8^T) / 2048  — FP8 tensor GEMM
    k_ogemm<<<dim3(18, 1, 16), 256, SMEM_DYN>>>(et, gn8, oT);

    // output convs + residual
    k_outconv<<<dim3(18, 4, 16), 256, SMEM_DYN>>>(Wc, oT, bfav, bfah, x, out_v, out_h);
}

// round 12
// speedup vs baseline: 1.0776x; 1.0776x over previous
#include <cuda_runtime.h>
#include <cuda_bf16.h>
#include <cstdint>

typedef unsigned int u32;
typedef unsigned long long u64;

#define BB   8
#define CIN  512
#define MIDC 128
#define NNE  2304
#define SCALE_S 0.08838834764831845f
#define SCALE_E 0.125f            // E' = E/8 stored in e4m3
#define INV_OSCALE (1.0f/2048.0f) // 1/(SCALE_E * 16384)

// ---------------- scratch layout (bytes) ----------------
#define XT_SZ   ((size_t)3*BB*NNE*CIN*2)
#define FT_ONE  ((size_t)BB*NNE*MIDC*2)
#define G_SZ    ((size_t)2*BB*MIDC*NNE*4)
#define GN_SZ   ((size_t)2*BB*MIDC*NNE*2)   // fp8 uses half
#define ET_SZ   ((size_t)2*BB*NNE*NNE*2)    // fp8 uses half
#define Z_SZ    ((size_t)2*BB*NNE*4)
#define OT_SZ   ((size_t)2*BB*NNE*MIDC*2)
#define WC_SZ   ((size_t)6*65536*2)

#define XT_OFF  0ull
#define FT_OFF  (XT_OFF + XT_SZ)
#define G_OFF   (FT_OFF + 3*FT_ONE)
#define GN_OFF  (G_OFF + G_SZ)
#define ET_OFF  (GN_OFF + GN_SZ)
#define Z_OFF   (ET_OFF + ET_SZ)
#define OT_OFF  (Z_OFF + Z_SZ)
#define WC_OFF  (OT_OFF + OT_SZ)
#define TOTAL_SCRATCH (WC_OFF + WC_SZ)

__device__ __align__(1024) char d_scratch[TOTAL_SCRATCH];

// ---------------- MMA building blocks ----------------
__device__ __forceinline__ u32 pack_bf16(float lo, float hi) {
    u32 r; asm("cvt.rn.bf16x2.f32 %0, %1, %2;" : "=r"(r) : "f"(hi), "f"(lo)); return r;
}
__device__ __forceinline__ unsigned short pack_e4m3(float lo, float hi) {
    unsigned short r;
    asm("cvt.rn.satfinite.e4m3x2.f32 %0, %1, %2;" : "=h"(r) : "f"(hi), "f"(lo));
    return r;
}
__device__ __forceinline__ void cpasync16(u32 saddr, const void* g) {
    asm volatile("cp.async.cg.shared.global [%0], [%1], 16;" :: "r"(saddr), "l"(g));
}
#define CP_COMMIT() asm volatile("cp.async.commit_group;" ::: "memory")

__device__ __forceinline__ void ldsm_x4(u32 a, u32& r0, u32& r1, u32& r2, u32& r3) {
    asm volatile("ldmatrix.sync.aligned.m8n8.x4.shared.b16 {%0,%1,%2,%3}, [%4];"
                 : "=r"(r0), "=r"(r1), "=r"(r2), "=r"(r3) : "r"(a));
}
__device__ __forceinline__ void mma16816(float c[4], const u32 a[4], u32 b0, u32 b1) {
    asm volatile("mma.sync.aligned.m16n8k16.row.col.f32.bf16.bf16.f32 "
                 "{%0,%1,%2,%3}, {%4,%5,%6,%7}, {%8,%9}, {%0,%1,%2,%3};"
                 : "+f"(c[0]), "+f"(c[1]), "+f"(c[2]), "+f"(c[3])
                 : "r"(a[0]), "r"(a[1]), "r"(a[2]), "r"(a[3]), "r"(b0), "r"(b1));
}
__device__ __forceinline__ void mma16832_fp8(float c[4], const u32 a[4], u32 b0, u32 b1) {
    asm volatile("mma.sync.aligned.m16n8k32.row.col.f32.e4m3.e4m3.f32 "
                 "{%0,%1,%2,%3}, {%4,%5,%6,%7}, {%8,%9}, {%0,%1,%2,%3};"
                 : "+f"(c[0]), "+f"(c[1]), "+f"(c[2]), "+f"(c[3])
                 : "r"(a[0]), "r"(a[1]), "r"(a[2]), "r"(a[3]), "r"(b0), "r"(b1));
}

// Tile: 128 rows x 128 B (bf16: 64 elems; fp8: 128 elems). 8 x 16B chunks/row.
// Swizzle cc = c ^ (r&7) — conflict-free for cp.async stores and ldmatrix reads.
#define TILE_B 16384
#define NSTAGE 3

__device__ __forceinline__ u32 sw64(int r, int ch) {
    return (u32)(r * 128 + ((ch ^ (r & 7)) << 4));
}

// 256 threads: thread -> row tid>>1, 4 x 16B chunks. pitch/offset in BYTES.
__device__ __forceinline__ void tile_load(u32 sdst, const char* src,
                                          size_t pitchB, int k0B, int tid) {
    int r = tid >> 1;
    const char* g = src + (size_t)r * pitchB + k0B;
#pragma unroll
    for (int i = 0; i < 4; i++) {
        int c = (tid & 1) * 4 + i;
        cpasync16(sdst + sw64(r, c), g + c * 16);
    }
}

// CTA 128x128 bf16 GEMM: acc += A(128 x Kd) · B(128 x Kd)^T, k-major operands.
__device__ __forceinline__ void hmma_gemm(
    u32 sA, u32 sB,
    const __nv_bfloat16* __restrict__ A, size_t pA,
    const __nv_bfloat16* __restrict__ B, size_t pB,
    int Kd, int tid, float acc[4][4][4])
{
#pragma unroll
    for (int i = 0; i < 4; i++)
#pragma unroll
        for (int j = 0; j < 4; j++)
#pragma unroll
            for (int e = 0; e < 4; e++) acc[i][j][e] = 0.f;

    const int lane = tid & 31, wid = tid >> 5;
    const int wm = wid & 1, wn = wid >> 1;
    const int T = Kd / 64;
    const char* Ab = (const char*)A;
    const char* Bb = (const char*)B;
    const size_t pAB = pA * 2, pBB = pB * 2;

    tile_load(sA, Ab, pAB, 0, tid);
    tile_load(sB, Bb, pBB, 0, tid);
    CP_COMMIT();
    if (T > 1) {
        tile_load(sA + TILE_B, Ab, pAB, 128, tid);
        tile_load(sB + TILE_B, Bb, pBB, 128, tid);
    }
    CP_COMMIT();

    int slot_next = 2 % NSTAGE;
    for (int t = 0; t < T; t++) {
        asm volatile("cp.async.wait_group 1;" ::: "memory");
        __syncthreads();
        if (t + 2 < T) {
            tile_load(sA + slot_next * TILE_B, Ab, pAB, (t + 2) * 128, tid);
            tile_load(sB + slot_next * TILE_B, Bb, pBB, (t + 2) * 128, tid);
        }
        CP_COMMIT();
        slot_next = (slot_next + 1 == NSTAGE) ? 0 : slot_next + 1;

        const int cur = t % NSTAGE;
        const u32 abuf = sA + cur * TILE_B;
        const u32 bbuf = sB + cur * TILE_B;
#pragma unroll
        for (int k16 = 0; k16 < 4; k16++) {
            u32 a[4][4];
#pragma unroll
            for (int f = 0; f < 4; f++) {
                int row = wm * 64 + f * 16 + (lane & 15);
                int ch  = k16 * 2 + (lane >> 4);
                ldsm_x4(abuf + sw64(row, ch), a[f][0], a[f][1], a[f][2], a[f][3]);
            }
            u32 b[4][2];
#pragma unroll
            for (int p = 0; p < 2; p++) {
                int row = wn * 32 + p * 16 + ((lane & 16) >> 1) + (lane & 7);
                int ch  = k16 * 2 + ((lane >> 3) & 1);
                ldsm_x4(bbuf + sw64(row, ch), b[2 * p][0], b[2 * p][1],
                        b[2 * p + 1][0], b[2 * p + 1][1]);
            }
#pragma unroll
            for (int mf = 0; mf < 4; mf++)
#pragma unroll
                for (int nf = 0; nf < 4; nf++)
                    mma16816(acc[mf][nf], a[mf], b[nf][0], b[nf][1]);
        }
    }
}

// CTA 128x128 FP8 GEMM: e4m3 operands, k32 steps, BK=128 bytes.
__device__ __forceinline__ void qmma_gemm(
    u32 sA, u32 sB,
    const char* __restrict__ A, size_t pAB,
    const char* __restrict__ B, size_t pBB,
    int KdB, int tid, float acc[4][4][4])
{
#pragma unroll
    for (int i = 0; i < 4; i++)
#pragma unroll
        for (int j = 0; j < 4; j++)
#pragma unroll
            for (int e = 0; e < 4; e++) acc[i][j][e] = 0.f;

    const int lane = tid & 31, wid = tid >> 5;
    const int wm = wid & 1, wn = wid >> 1;
    const int T = KdB / 128;

    tile_load(sA, A, pAB, 0, tid);
    tile_load(sB, B, pBB, 0, tid);
    CP_COMMIT();
    if (T > 1) {
        tile_load(sA + TILE_B, A, pAB, 128, tid);
        tile_load(sB + TILE_B, B, pBB, 128, tid);
    }
    CP_COMMIT();

    int slot_next = 2 % NSTAGE;
    for (int t = 0; t < T; t++) {
        asm volatile("cp.async.wait_group 1;" ::: "memory");
        __syncthreads();
        if (t + 2 < T) {
            tile_load(sA + slot_next * TILE_B, A, pAB, (t + 2) * 128, tid);
            tile_load(sB + slot_next * TILE_B, B, pBB, (t + 2) * 128, tid);
        }
        CP_COMMIT();
        slot_next = (slot_next + 1 == NSTAGE) ? 0 : slot_next + 1;

        const int cur = t % NSTAGE;
        const u32 abuf = sA + cur * TILE_B;
        const u32 bbuf = sB + cur * TILE_B;
#pragma unroll
        for (int k32 = 0; k32 < 4; k32++) {
            u32 a[4][4];
#pragma unroll
            for (int f = 0; f < 4; f++) {
                int row = wm * 64 + f * 16 + (lane & 15);
                int ch  = k32 * 2 + (lane >> 4);
                ldsm_x4(abuf + sw64(row, ch), a[f][0], a[f][1], a[f][2], a[f][3]);
            }
            u32 b[4][2];
#pragma unroll
            for (int p = 0; p < 2; p++) {
                int row = wn * 32 + p * 16 + ((lane & 16) >> 1) + (lane & 7);
                int ch  = k32 * 2 + ((lane >> 3) & 1);
                ldsm_x4(bbuf + sw64(row, ch), b[2 * p][0], b[2 * p][1],
                        b[2 * p + 1][0], b[2 * p + 1][1]);
            }
#pragma unroll
            for (int mf = 0; mf < 4; mf++)
#pragma unroll
                for (int nf = 0; nf < 4; nf++)
                    mma16832_fp8(acc[mf][nf], a[mf], b[nf][0], b[nf][1]);
        }
    }
}

#define SMEM_DYN (2 * NSTAGE * TILE_B)   // 96 KB

// ============================ SIMT prep ============================
__global__ __launch_bounds__(256) void transpose_x(
    const float* __restrict__ x, const float* __restrict__ x_v,
    const float* __restrict__ x_h, __nv_bfloat16* __restrict__ xT)
{
    __shared__ float t[32][33];
    int z = blockIdx.z, tt = z >> 3, b = z & 7;
    const float* src = (tt == 0) ? x : (tt == 1 ? x_v : x_h);
    int n0 = blockIdx.x * 32, c0 = blockIdx.y * 32;
    int tx = threadIdx.x & 31, ty8 = threadIdx.x >> 5;
#pragma unroll
    for (int i = 0; i < 4; i++)
        t[ty8 + i * 8][tx] = src[((size_t)b * CIN + c0 + ty8 + i * 8) * NNE + n0 + tx];
    __syncthreads();
#pragma unroll
    for (int i = 0; i < 4; i++)
        xT[(((size_t)tt * BB + b) * NNE + n0 + ty8 + i * 8) * CIN + c0 + tx] =
            __float2bfloat16(t[tx][ty8 + i * 8]);
}

struct WC6 { const float* s[6]; };
__global__ __launch_bounds__(256) void conv_weights(WC6 w, __nv_bfloat16* __restrict__ dst,
                                                    float* __restrict__ Z)
{
    int idx = blockIdx.x * 256 + threadIdx.x;
    int t = idx >> 16, i = idx & 65535;
    dst[(size_t)t * 65536 + i] = __float2bfloat16(w.s[t][i]);
    if (idx < 2 * BB * NNE) Z[idx] = 0.f;
}

// gn8[idx] = e4m3(g * 16384 / Z[n])  (2 elems/thread)
__global__ __launch_bounds__(256) void gnorm(
    const float* __restrict__ g, const float* __restrict__ Z,
    unsigned char* __restrict__ gn8)
{
    size_t idx = ((size_t)blockIdx.x * 256 + threadIdx.x) * 2;
    int n = (int)(idx % NNE);
    size_t sb = idx / ((size_t)NNE * MIDC);
    const float* zr = Z + sb * NNE;
    float v0 = g[idx]     * __frcp_rn(zr[n])     * 16384.f;
    float v1 = g[idx + 1] * __frcp_rn(zr[n + 1]) * 16384.f;
    *reinterpret_cast<unsigned short*>(gn8 + idx) = pack_e4m3(v0, v1);
}

// ============================ tensor kernels ============================

// f[o][b][n][m] = relu(BN(xT·W^T)). grid (18, BB, 3).
__global__ __launch_bounds__(256, 2) void k_fconv(
    const __nv_bfloat16* __restrict__ xT, const __nv_bfloat16* __restrict__ Wc,
    const float* __restrict__ ba, const float* __restrict__ ga, const float* __restrict__ ta,
    const float* __restrict__ bv, const float* __restrict__ gv, const float* __restrict__ tv,
    __nv_bfloat16* __restrict__ ft)
{
    extern __shared__ char dsm[];
    __shared__ float sS[128], sC[128];
    int tid = threadIdx.x, lane = tid & 31, wid = tid >> 5;
    int wm = wid & 1, wn = wid >> 1;
    int nt = blockIdx.x, b = blockIdx.y, o = blockIdx.z;

    if (tid < 128) {
        const float* bias  = (o == 0) ? ba : bv;
        const float* gamma = (o == 0) ? ga : gv;
        const float* beta  = (o == 0) ? ta : tv;
        float s = gamma[tid] * rsqrtf(1.f + 1e-5f);
        sS[tid] = s; sC[tid] = bias[tid] * s + beta[tid];
    }

    const __nv_bfloat16* A = xT + (((size_t)o * BB + b) * NNE + (size_t)nt * 128) * CIN;
    const __nv_bfloat16* B = Wc + (size_t)((o == 0) ? 0 : 1) * 65536;

    float acc[4][4][4];
    u32 sA = (u32)__cvta_generic_to_shared(dsm);
    u32 sB = sA + NSTAGE * TILE_B;
    hmma_gemm(sA, sB, A, CIN, B, CIN, CIN, tid, acc);

    __nv_bfloat16* dst = ft + (size_t)o * (size_t)BB * NNE * MIDC
                            + ((size_t)b * NNE + (size_t)nt * 128) * MIDC;
#pragma unroll
    for (int mf = 0; mf < 4; mf++)
#pragma unroll
        for (int nf = 0; nf < 4; nf++)
#pragma unroll
            for (int h = 0; h < 2; h++) {
                int r = wm * 64 + mf * 16 + (lane >> 2) + h * 8;
                int c = wn * 32 + nf * 8 + ((lane & 3) << 1);
                float y0 = fmaxf(acc[mf][nf][h * 2]     * sS[c]     + sC[c],     0.f);
                float y1 = fmaxf(acc[mf][nf][h * 2 + 1] * sS[c + 1] + sC[c + 1], 0.f);
                *reinterpret_cast<u32*>(dst + (size_t)r * MIDC + c) = pack_bf16(y0, y1);
            }
}

// g[sel][b][m][n] = Wg·xT^T + bias (fp32). grid (18, BB, 2).
__global__ __launch_bounds__(256, 2) void k_gconv(
    const __nv_bfloat16* __restrict__ xT, const __nv_bfloat16* __restrict__ Wc,
    const float* __restrict__ bgav, const float* __restrict__ bgah,
    float* __restrict__ g)
{
    extern __shared__ char dsm[];
    int tid = threadIdx.x, lane = tid & 31, wid = tid >> 5;
    int wm = wid & 1, wn = wid >> 1;
    int nt = blockIdx.x, b = blockIdx.y, o = blockIdx.z;

    const __nv_bfloat16* A = Wc + (size_t)(2 + o) * 65536;
    const __nv_bfloat16* B = xT + ((size_t)b * NNE + (size_t)nt * 128) * CIN;

    float acc[4][4][4];
    u32 sA = (u32)__cvta_generic_to_shared(dsm);
    u32 sB = sA + NSTAGE * TILE_B;
    hmma_gemm(sA, sB, A, CIN, B, CIN, CIN, tid, acc);

    const float* bias = (o == 0) ? bgav : bgah;
    float* dst = g + (size_t)(o * BB + b) * MIDC * NNE + (size_t)nt * 128;
#pragma unroll
    for (int mf = 0; mf < 4; mf++)
#pragma unroll
        for (int nf = 0; nf < 4; nf++)
#pragma unroll
            for (int h = 0; h < 2; h++) {
                int r = wm * 64 + mf * 16 + (lane >> 2) + h * 8;
                int c = wn * 32 + nf * 8 + ((lane & 3) << 1);
                float bval = bias[r];
                *reinterpret_cast<float2*>(dst + (size_t)r * NNE + c) =
                    make_float2(acc[mf][nf][h * 2] + bval, acc[mf][nf][h * 2 + 1] + bval);
            }
}

// ET8[sel][b][j][i] = e4m3(exp(scale*fa[j]·fq[i]) * SCALE_E); Z[sel][b][i] += col sums.
// grid (it 18, jt 18, b + 8*sel). u32 stores via quad shuffle packing.
__global__ __launch_bounds__(256, 2) void k_score(
    const __nv_bfloat16* __restrict__ ft, unsigned char* __restrict__ et,
    float* __restrict__ Z)
{
    extern __shared__ char dsm[];
    __shared__ float zs[2][128];
    int tid = threadIdx.x, lane = tid & 31, wid = tid >> 5;
    int wm = wid & 1, wn = wid >> 1;
    int it = blockIdx.x, jt = blockIdx.y;
    int z = blockIdx.z, b = z & 7, sel = z >> 3;

    const __nv_bfloat16* fa = ft + (size_t)b * NNE * MIDC;
    const __nv_bfloat16* fq = ft + (size_t)(1 + sel) * (size_t)BB * NNE * MIDC
                                 + (size_t)b * NNE * MIDC;
    const __nv_bfloat16* A = fa + (size_t)jt * 128 * MIDC;
    const __nv_bfloat16* B = fq + (size_t)it * 128 * MIDC;

    float acc[4][4][4];
    u32 sA = (u32)__cvta_generic_to_shared(dsm);
    u32 sB = sA + NSTAGE * TILE_B;
    hmma_gemm(sA, sB, A, MIDC, B, MIDC, MIDC, tid, acc);

#pragma unroll
    for (int mf = 0; mf < 4; mf++)
#pragma unroll
        for (int nf = 0; nf < 4; nf++)
#pragma unroll
            for (int e = 0; e < 4; e++)
                acc[mf][nf][e] = __expf(acc[mf][nf][e] * SCALE_S);

    unsigned char* dst = et + ((size_t)(sel * BB + b) * NNE + (size_t)jt * 128) * NNE
                            + (size_t)it * 128;
    const bool even = ((lane & 1) == 0);
#pragma unroll
    for (int mf = 0; mf < 4; mf++)
#pragma unroll
        for (int nf = 0; nf < 4; nf++)
#pragma unroll
            for (int h = 0; h < 2; h++) {
                int r = wm * 64 + mf * 16 + (lane >> 2) + h * 8;
                u32 mine = (u32)pack_e4m3(acc[mf][nf][h * 2] * SCALE_E,
                                          acc[mf][nf][h * 2 + 1] * SCALE_E);
                u32 other = __shfl_xor_sync(0xffffffffu, mine, 1);
                if (even) {
                    // this lane owns cols c..c+1, partner owns c+2..c+3
                    int c = wn * 32 + nf * 8 + ((lane & 3) << 1);
                    *reinterpret_cast<u32*>(dst + (size_t)r * NNE + c) =
                        mine | (other << 16);
                }
            }

#pragma unroll
    for (int nf = 0; nf < 4; nf++) {
        float s0 = 0.f, s1 = 0.f;
#pragma unroll
        for (int mf = 0; mf < 4; mf++) {
            s0 += acc[mf][nf][0] + acc[mf][nf][2];
            s1 += acc[mf][nf][1] + acc[mf][nf][3];
        }
#pragma unroll
        for (int off = 4; off < 32; off <<= 1) {
            s0 += __shfl_xor_sync(0xffffffffu, s0, off);
            s1 += __shfl_xor_sync(0xffffffffu, s1, off);
        }
        if (lane < 4) {
            int c = wn * 32 + nf * 8 + lane * 2;
            zs[wm][c] = s0;
            zs[wm][c + 1] = s1;
        }
    }
    __syncthreads();
    if (tid < 128)
        atomicAdd(&Z[(size_t)(sel * BB + b) * NNE + (size_t)it * 128 + tid],
                  zs[0][tid] + zs[1][tid]);
}

// oT[sel][b][j][m] = (1/2048) * sum_i ET8[j][i]·gn8[m][i]  — FP8 GEMM.
// grid (jt 18, 1, b+8*sel).
__global__ __launch_bounds__(256, 2) void k_ogemm(
    const unsigned char* __restrict__ et, const unsigned char* __restrict__ gn8,
    __nv_bfloat16* __restrict__ oT)
{
    extern __shared__ char dsm[];
    int tid = threadIdx.x, lane = tid & 31, wid = tid >> 5;
    int wm = wid & 1, wn = wid >> 1;
    int jt = blockIdx.x;
    int z = blockIdx.z, b = z & 7, sel = z >> 3;

    const char* A = (const char*)et + ((size_t)(sel * BB + b) * NNE + (size_t)jt * 128) * NNE;
    const char* B = (const char*)gn8 + (size_t)(sel * BB + b) * MIDC * NNE;

    float acc[4][4][4];
    u32 sA = (u32)__cvta_generic_to_shared(dsm);
    u32 sB = sA + NSTAGE * TILE_B;
    qmma_gemm(sA, sB, A, NNE, B, NNE, NNE, tid, acc);

    __nv_bfloat16* dst = oT + ((size_t)(sel * BB + b) * NNE + (size_t)jt * 128) * MIDC;
#pragma unroll
    for (int mf = 0; mf < 4; mf++)
#pragma unroll
        for (int nf = 0; nf < 4; nf++)
#pragma unroll
            for (int h = 0; h < 2; h++) {
                int r = wm * 64 + mf * 16 + (lane >> 2) + h * 8;
                int c = wn * 32 + nf * 8 + ((lane & 3) << 1);
                *reinterpret_cast<u32*>(dst + (size_t)r * MIDC + c) =
                    pack_bf16(acc[mf][nf][h * 2] * INV_OSCALE,
                              acc[mf][nf][h * 2 + 1] * INV_OSCALE);
            }
}

// out[sel][b][cout][n] = Wf·oT^T + bias + x. grid (nt 18, ct 4, b+8*sel).
__global__ __launch_bounds__(256, 2) void k_outconv(
    const __nv_bfloat16* __restrict__ Wc, const __nv_bfloat16* __restrict__ oT,
    const float* __restrict__ bfav, const float* __restrict__ bfah,
    const float* __restrict__ x,
    float* __restrict__ out_v, float* __restrict__ out_h)
{
    extern __shared__ char dsm[];
    int tid = threadIdx.x, lane = tid & 31, wid = tid >> 5;
    int wm = wid & 1, wn = wid >> 1;
    int nt = blockIdx.x, ct = blockIdx.y;
    int z = blockIdx.z, b = z & 7, sel = z >> 3;

    const __nv_bfloat16* A = Wc + (size_t)(4 + sel) * 65536 + (size_t)ct * 128 * MIDC;
    const __nv_bfloat16* B = oT + ((size_t)(sel * BB + b) * NNE + (size_t)nt * 128) * MIDC;

    float acc[4][4][4];
    u32 sA = (u32)__cvta_generic_to_shared(dsm);
    u32 sB = sA + NSTAGE * TILE_B;
    hmma_gemm(sA, sB, A, MIDC, B, MIDC, MIDC, tid, acc);

    const float* bias = (sel == 0) ? bfav : bfah;
    float* outp = (sel == 0) ? out_v : out_h;
#pragma unroll
    for (int mf = 0; mf < 4; mf++)
#pragma unroll
        for (int nf = 0; nf < 4; nf++)
#pragma unroll
            for (int h = 0; h < 2; h++) {
                int r = wm * 64 + mf * 16 + (lane >> 2) + h * 8;
                int c = wn * 32 + nf * 8 + ((lane & 3) << 1);
                int cout = ct * 128 + r;
                size_t base = ((size_t)b * CIN + cout) * NNE + (size_t)nt * 128 + c;
                float2 xv = *reinterpret_cast<const float2*>(x + base);
                float bval = bias[cout];
                *reinterpret_cast<float2*>(outp + base) =
                    make_float2(acc[mf][nf][h * 2] + bval + xv.x,
                                acc[mf][nf][h * 2 + 1] + bval + xv.y);
            }
}

// ============================================================================
extern "C" void kernel_launch(void* const* d_in, const int* in_sizes, int n_in,
                              void* d_out, int out_size)
{
    (void)in_sizes; (void)n_in; (void)out_size;

    const float* x    = (const float*)d_in[0];
    const float* x_h  = (const float*)d_in[1];
    const float* x_v  = (const float*)d_in[2];
    const float* Wa   = (const float*)d_in[3];
    const float* ba   = (const float*)d_in[4];
    const float* ga   = (const float*)d_in[5];
    const float* ta   = (const float*)d_in[6];
    const float* Wv   = (const float*)d_in[7];
    const float* bv   = (const float*)d_in[8];
    const float* gv   = (const float*)d_in[9];
    const float* tv   = (const float*)d_in[10];
    const float* Wgav = (const float*)d_in[11];
    const float* bgav = (const float*)d_in[12];
    const float* Wgah = (const float*)d_in[13];
    const float* bgah = (const float*)d_in[14];
    const float* Wfav = (const float*)d_in[15];
    const float* bfav = (const float*)d_in[16];
    const float* Wfah = (const float*)d_in[17];
    const float* bfah = (const float*)d_in[18];

    void* sp = nullptr;
    cudaGetSymbolAddress(&sp, d_scratch);
    char* base = (char*)sp;
    __nv_bfloat16* xT  = (__nv_bfloat16*)(base + XT_OFF);
    __nv_bfloat16* ft  = (__nv_bfloat16*)(base + FT_OFF);
    float*         g   = (float*)(base + G_OFF);
    unsigned char* gn8 = (unsigned char*)(base + GN_OFF);
    unsigned char* et  = (unsigned char*)(base + ET_OFF);
    float*         Zp  = (float*)(base + Z_OFF);
    __nv_bfloat16* oT  = (__nv_bfloat16*)(base + OT_OFF);
    __nv_bfloat16* Wc  = (__nv_bfloat16*)(base + WC_OFF);

    float* out_h = (float*)d_out;
    float* out_v = out_h + (size_t)BB * CIN * NNE;

    static int attr_done = 0;
    if (!attr_done) {
        cudaFuncSetAttribute(k_fconv,   cudaFuncAttributeMaxDynamicSharedMemorySize, SMEM_DYN);
        cudaFuncSetAttribute(k_gconv,   cudaFuncAttributeMaxDynamicSharedMemorySize, SMEM_DYN);
        cudaFuncSetAttribute(k_score,   cudaFuncAttributeMaxDynamicSharedMemorySize, SMEM_DYN);
        cudaFuncSetAttribute(k_ogemm,   cudaFuncAttributeMaxDynamicSharedMemorySize, SMEM_DYN);
        cudaFuncSetAttribute(k_outconv, cudaFuncAttributeMaxDynamicSharedMemorySize, SMEM_DYN);
        attr_done = 1;
    }

    // prep: transpose x to bf16 [n][c]; weights to bf16; zero Z
    transpose_x<<<dim3(NNE / 32, CIN / 32, 3 * BB), 256>>>(x, x_v, x_h, xT);
    WC6 w = {{ Wa, Wv, Wgav, Wgah, Wfav, Wfah }};
    conv_weights<<<1536, 256>>>(w, Wc, Zp);

    // input convs
    k_fconv<<<dim3(18, BB, 3), 256, SMEM_DYN>>>(xT, Wc, ba, ga, ta, bv, gv, tv, ft);
    k_gconv<<<dim3(18, BB, 2), 256, SMEM_DYN>>>(xT, Wc, bgav, bgah, g);

    // scores: ET8 = e4m3(exp(scale*S)/8)^T, Z = per-query sums (fp32)
    k_score<<<dim3(18, 18, 16), 256, SMEM_DYN>>>(ft, et, Zp);

    // fold 16384/Z into g -> e4m3
    gnorm<<<(2 * BB * MIDC * NNE) / 512, 256>>>(g, Zp, gn8);

    // oT = (ET8 · gn8^T) / 2048  — FP8 tensor GEMM
    k_ogemm<<<dim3(18, 1, 16), 256, SMEM_DYN>>>(et, gn8, oT);

    // output convs + residual
    k_outconv<<<dim3(18, 4, 16), 256, SMEM_DYN>>>(Wc, oT, bfav, bfah, x, out_v, out_h);
}

// round 13
// speedup vs baseline: 1.1305x; 1.0491x over previous
#include <cuda_runtime.h>
#include <cuda_bf16.h>
#include <cstdint>

typedef unsigned int u32;
typedef unsigned long long u64;

#define BB   8
#define CIN  512
#define MIDC 128
#define NNE  2304
#define SCALE_S 0.08838834764831845f
#define SCALE_E 0.125f            // E' = E/8 stored in e4m3
#define INV_OSCALE (1.0f/2048.0f) // 1/(SCALE_E * 16384)

// ---------------- scratch layout (bytes) ----------------
#define XT_SZ   ((size_t)3*BB*NNE*CIN*2)
#define FT_ONE  ((size_t)BB*NNE*MIDC)       // fp8 now
#define G_SZ    ((size_t)2*BB*MIDC*NNE*2)   // bf16 now
#define GN_SZ   ((size_t)2*BB*MIDC*NNE)     // fp8
#define ET_SZ   ((size_t)2*BB*NNE*NNE)      // fp8
#define Z_SZ    ((size_t)2*BB*NNE*4)
#define OT_SZ   ((size_t)2*BB*NNE*MIDC*2)
#define WC_SZ   ((size_t)6*65536*2)

#define XT_OFF  0ull
#define FT_OFF  (XT_OFF + XT_SZ)
#define G_OFF   (FT_OFF + 3*FT_ONE)
#define GN_OFF  (G_OFF + G_SZ)
#define ET_OFF  (GN_OFF + GN_SZ)
#define Z_OFF   (ET_OFF + ET_SZ)
#define OT_OFF  (Z_OFF + Z_SZ)
#define WC_OFF  (OT_OFF + OT_SZ)
#define TOTAL_SCRATCH (WC_OFF + WC_SZ)

__device__ __align__(1024) char d_scratch[TOTAL_SCRATCH];

// ---------------- MMA building blocks ----------------
__device__ __forceinline__ u32 pack_bf16(float lo, float hi) {
    u32 r; asm("cvt.rn.bf16x2.f32 %0, %1, %2;" : "=r"(r) : "f"(hi), "f"(lo)); return r;
}
__device__ __forceinline__ unsigned short pack_e4m3(float lo, float hi) {
    unsigned short r;
    asm("cvt.rn.satfinite.e4m3x2.f32 %0, %1, %2;" : "=h"(r) : "f"(hi), "f"(lo));
    return r;
}
__device__ __forceinline__ void cpasync16(u32 saddr, const void* g) {
    asm volatile("cp.async.cg.shared.global [%0], [%1], 16;" :: "r"(saddr), "l"(g));
}
#define CP_COMMIT() asm volatile("cp.async.commit_group;" ::: "memory")

__device__ __forceinline__ void ldsm_x4(u32 a, u32& r0, u32& r1, u32& r2, u32& r3) {
    asm volatile("ldmatrix.sync.aligned.m8n8.x4.shared.b16 {%0,%1,%2,%3}, [%4];"
                 : "=r"(r0), "=r"(r1), "=r"(r2), "=r"(r3) : "r"(a));
}
__device__ __forceinline__ void mma16816(float c[4], const u32 a[4], u32 b0, u32 b1) {
    asm volatile("mma.sync.aligned.m16n8k16.row.col.f32.bf16.bf16.f32 "
                 "{%0,%1,%2,%3}, {%4,%5,%6,%7}, {%8,%9}, {%0,%1,%2,%3};"
                 : "+f"(c[0]), "+f"(c[1]), "+f"(c[2]), "+f"(c[3])
                 : "r"(a[0]), "r"(a[1]), "r"(a[2]), "r"(a[3]), "r"(b0), "r"(b1));
}
__device__ __forceinline__ void mma16832_fp8(float c[4], const u32 a[4], u32 b0, u32 b1) {
    asm volatile("mma.sync.aligned.m16n8k32.row.col.f32.e4m3.e4m3.f32 "
                 "{%0,%1,%2,%3}, {%4,%5,%6,%7}, {%8,%9}, {%0,%1,%2,%3};"
                 : "+f"(c[0]), "+f"(c[1]), "+f"(c[2]), "+f"(c[3])
                 : "r"(a[0]), "r"(a[1]), "r"(a[2]), "r"(a[3]), "r"(b0), "r"(b1));
}

// Tile: 128 rows x 128 B. 8 x 16B chunks/row. Swizzle cc = c ^ (r&7).
#define TILE_B 16384
#define NSTAGE 3

__device__ __forceinline__ u32 sw64(int r, int ch) {
    return (u32)(r * 128 + ((ch ^ (r & 7)) << 4));
}

// 256 threads: thread -> row tid>>1, 4 x 16B chunks. pitch/offset in BYTES.
__device__ __forceinline__ void tile_load(u32 sdst, const char* src,
                                          size_t pitchB, int k0B, int tid) {
    int r = tid >> 1;
    const char* g = src + (size_t)r * pitchB + k0B;
#pragma unroll
    for (int i = 0; i < 4; i++) {
        int c = (tid & 1) * 4 + i;
        cpasync16(sdst + sw64(r, c), g + c * 16);
    }
}

// CTA 128x128 bf16 GEMM: acc += A(128 x Kd) · B(128 x Kd)^T, k-major operands.
__device__ __forceinline__ void hmma_gemm(
    u32 sA, u32 sB,
    const __nv_bfloat16* __restrict__ A, size_t pA,
    const __nv_bfloat16* __restrict__ B, size_t pB,
    int Kd, int tid, float acc[4][4][4])
{
#pragma unroll
    for (int i = 0; i < 4; i++)
#pragma unroll
        for (int j = 0; j < 4; j++)
#pragma unroll
            for (int e = 0; e < 4; e++) acc[i][j][e] = 0.f;

    const int lane = tid & 31, wid = tid >> 5;
    const int wm = wid & 1, wn = wid >> 1;
    const int T = Kd / 64;
    const char* Ab = (const char*)A;
    const char* Bb = (const char*)B;
    const size_t pAB = pA * 2, pBB = pB * 2;

    tile_load(sA, Ab, pAB, 0, tid);
    tile_load(sB, Bb, pBB, 0, tid);
    CP_COMMIT();
    if (T > 1) {
        tile_load(sA + TILE_B, Ab, pAB, 128, tid);
        tile_load(sB + TILE_B, Bb, pBB, 128, tid);
    }
    CP_COMMIT();

    int slot_next = 2 % NSTAGE;
    for (int t = 0; t < T; t++) {
        asm volatile("cp.async.wait_group 1;" ::: "memory");
        __syncthreads();
        if (t + 2 < T) {
            tile_load(sA + slot_next * TILE_B, Ab, pAB, (t + 2) * 128, tid);
            tile_load(sB + slot_next * TILE_B, Bb, pBB, (t + 2) * 128, tid);
        }
        CP_COMMIT();
        slot_next = (slot_next + 1 == NSTAGE) ? 0 : slot_next + 1;

        const int cur = t % NSTAGE;
        const u32 abuf = sA + cur * TILE_B;
        const u32 bbuf = sB + cur * TILE_B;
#pragma unroll
        for (int k16 = 0; k16 < 4; k16++) {
            u32 a[4][4];
#pragma unroll
            for (int f = 0; f < 4; f++) {
                int row = wm * 64 + f * 16 + (lane & 15);
                int ch  = k16 * 2 + (lane >> 4);
                ldsm_x4(abuf + sw64(row, ch), a[f][0], a[f][1], a[f][2], a[f][3]);
            }
            u32 b[4][2];
#pragma unroll
            for (int p = 0; p < 2; p++) {
                int row = wn * 32 + p * 16 + ((lane & 16) >> 1) + (lane & 7);
                int ch  = k16 * 2 + ((lane >> 3) & 1);
                ldsm_x4(bbuf + sw64(row, ch), b[2 * p][0], b[2 * p][1],
                        b[2 * p + 1][0], b[2 * p + 1][1]);
            }
#pragma unroll
            for (int mf = 0; mf < 4; mf++)
#pragma unroll
                for (int nf = 0; nf < 4; nf++)
                    mma16816(acc[mf][nf], a[mf], b[nf][0], b[nf][1]);
        }
    }
}

// CTA 128x128 FP8 GEMM: e4m3 operands, k32 steps, BK=128 bytes.
__device__ __forceinline__ void qmma_gemm(
    u32 sA, u32 sB,
    const char* __restrict__ A, size_t pAB,
    const char* __restrict__ B, size_t pBB,
    int KdB, int tid, float acc[4][4][4])
{
#pragma unroll
    for (int i = 0; i < 4; i++)
#pragma unroll
        for (int j = 0; j < 4; j++)
#pragma unroll
            for (int e = 0; e < 4; e++) acc[i][j][e] = 0.f;

    const int lane = tid & 31, wid = tid >> 5;
    const int wm = wid & 1, wn = wid >> 1;
    const int T = KdB / 128;

    tile_load(sA, A, pAB, 0, tid);
    tile_load(sB, B, pBB, 0, tid);
    CP_COMMIT();
    if (T > 1) {
        tile_load(sA + TILE_B, A, pAB, 128, tid);
        tile_load(sB + TILE_B, B, pBB, 128, tid);
    }
    CP_COMMIT();

    int slot_next = 2 % NSTAGE;
    for (int t = 0; t < T; t++) {
        asm volatile("cp.async.wait_group 1;" ::: "memory");
        __syncthreads();
        if (t + 2 < T) {
            tile_load(sA + slot_next * TILE_B, A, pAB, (t + 2) * 128, tid);
            tile_load(sB + slot_next * TILE_B, B, pBB, (t + 2) * 128, tid);
        }
        CP_COMMIT();
        slot_next = (slot_next + 1 == NSTAGE) ? 0 : slot_next + 1;

        const int cur = t % NSTAGE;
        const u32 abuf = sA + cur * TILE_B;
        const u32 bbuf = sB + cur * TILE_B;
#pragma unroll
        for (int k32 = 0; k32 < 4; k32++) {
            u32 a[4][4];
#pragma unroll
            for (int f = 0; f < 4; f++) {
                int row = wm * 64 + f * 16 + (lane & 15);
                int ch  = k32 * 2 + (lane >> 4);
                ldsm_x4(abuf + sw64(row, ch), a[f][0], a[f][1], a[f][2], a[f][3]);
            }
            u32 b[4][2];
#pragma unroll
            for (int p = 0; p < 2; p++) {
                int row = wn * 32 + p * 16 + ((lane & 16) >> 1) + (lane & 7);
                int ch  = k32 * 2 + ((lane >> 3) & 1);
                ldsm_x4(bbuf + sw64(row, ch), b[2 * p][0], b[2 * p][1],
                        b[2 * p + 1][0], b[2 * p + 1][1]);
            }
#pragma unroll
            for (int mf = 0; mf < 4; mf++)
#pragma unroll
                for (int nf = 0; nf < 4; nf++)
                    mma16832_fp8(acc[mf][nf], a[mf], b[nf][0], b[nf][1]);
        }
    }
}

#define SMEM_DYN (2 * NSTAGE * TILE_B)   // 96 KB

// ============================ SIMT prep ============================
__global__ __launch_bounds__(256) void transpose_x(
    const float* __restrict__ x, const float* __restrict__ x_v,
    const float* __restrict__ x_h, __nv_bfloat16* __restrict__ xT)
{
    __shared__ float t[32][33];
    int z = blockIdx.z, tt = z >> 3, b = z & 7;
    const float* src = (tt == 0) ? x : (tt == 1 ? x_v : x_h);
    int n0 = blockIdx.x * 32, c0 = blockIdx.y * 32;
    int tx = threadIdx.x & 31, ty8 = threadIdx.x >> 5;
#pragma unroll
    for (int i = 0; i < 4; i++)
        t[ty8 + i * 8][tx] = src[((size_t)b * CIN + c0 + ty8 + i * 8) * NNE + n0 + tx];
    __syncthreads();
#pragma unroll
    for (int i = 0; i < 4; i++)
        xT[(((size_t)tt * BB + b) * NNE + n0 + ty8 + i * 8) * CIN + c0 + tx] =
            __float2bfloat16(t[tx][ty8 + i * 8]);
}

struct WC6 { const float* s[6]; };
__global__ __launch_bounds__(256) void conv_weights(WC6 w, __nv_bfloat16* __restrict__ dst,
                                                    float* __restrict__ Z)
{
    int idx = blockIdx.x * 256 + threadIdx.x;
    int t = idx >> 16, i = idx & 65535;
    dst[(size_t)t * 65536 + i] = __float2bfloat16(w.s[t][i]);
    if (idx < 2 * BB * NNE) Z[idx] = 0.f;
}

// gn8[idx] = e4m3(g_bf16 * 16384 / Z[n])  (2 elems/thread)
__global__ __launch_bounds__(256) void gnorm(
    const __nv_bfloat16* __restrict__ g, const float* __restrict__ Z,
    unsigned char* __restrict__ gn8)
{
    size_t idx = ((size_t)blockIdx.x * 256 + threadIdx.x) * 2;
    int n = (int)(idx % NNE);
    size_t sb = idx / ((size_t)NNE * MIDC);
    const float* zr = Z + sb * NNE;
    float v0 = __bfloat162float(g[idx])     * __frcp_rn(zr[n])     * 16384.f;
    float v1 = __bfloat162float(g[idx + 1]) * __frcp_rn(zr[n + 1]) * 16384.f;
    *reinterpret_cast<unsigned short*>(gn8 + idx) = pack_e4m3(v0, v1);
}

// ============================ tensor kernels ============================

// ft8[o][b][n][m] = e4m3(relu(BN(xT·W^T))). grid (18, BB, 3).
__global__ __launch_bounds__(256, 2) void k_fconv(
    const __nv_bfloat16* __restrict__ xT, const __nv_bfloat16* __restrict__ Wc,
    const float* __restrict__ ba, const float* __restrict__ ga, const float* __restrict__ ta,
    const float* __restrict__ bv, const float* __restrict__ gv, const float* __restrict__ tv,
    unsigned char* __restrict__ ft)
{
    extern __shared__ char dsm[];
    __shared__ float sS[128], sC[128];
    int tid = threadIdx.x, lane = tid & 31, wid = tid >> 5;
    int wm = wid & 1, wn = wid >> 1;
    int nt = blockIdx.x, b = blockIdx.y, o = blockIdx.z;

    if (tid < 128) {
        const float* bias  = (o == 0) ? ba : bv;
        const float* gamma = (o == 0) ? ga : gv;
        const float* beta  = (o == 0) ? ta : tv;
        float s = gamma[tid] * rsqrtf(1.f + 1e-5f);
        sS[tid] = s; sC[tid] = bias[tid] * s + beta[tid];
    }

    const __nv_bfloat16* A = xT + (((size_t)o * BB + b) * NNE + (size_t)nt * 128) * CIN;
    const __nv_bfloat16* B = Wc + (size_t)((o == 0) ? 0 : 1) * 65536;

    float acc[4][4][4];
    u32 sA = (u32)__cvta_generic_to_shared(dsm);
    u32 sB = sA + NSTAGE * TILE_B;
    hmma_gemm(sA, sB, A, CIN, B, CIN, CIN, tid, acc);

    unsigned char* dst = ft + (size_t)o * (size_t)BB * NNE * MIDC
                            + ((size_t)b * NNE + (size_t)nt * 128) * MIDC;
    const bool even = ((lane & 1) == 0);
#pragma unroll
    for (int mf = 0; mf < 4; mf++)
#pragma unroll
        for (int nf = 0; nf < 4; nf++)
#pragma unroll
            for (int h = 0; h < 2; h++) {
                int r = wm * 64 + mf * 16 + (lane >> 2) + h * 8;
                int c = wn * 32 + nf * 8 + ((lane & 3) << 1);
                float y0 = fmaxf(acc[mf][nf][h * 2]     * sS[c]     + sC[c],     0.f);
                float y1 = fmaxf(acc[mf][nf][h * 2 + 1] * sS[c + 1] + sC[c + 1], 0.f);
                u32 mine = (u32)pack_e4m3(y0, y1);
                u32 other = __shfl_xor_sync(0xffffffffu, mine, 1);
                if (even)
                    *reinterpret_cast<u32*>(dst + (size_t)r * MIDC + c) =
                        mine | (other << 16);
            }
}

// g[sel][b][m][n] = Wg·xT^T + bias (bf16). grid (18, BB, 2).
__global__ __launch_bounds__(256, 2) void k_gconv(
    const __nv_bfloat16* __restrict__ xT, const __nv_bfloat16* __restrict__ Wc,
    const float* __restrict__ bgav, const float* __restrict__ bgah,
    __nv_bfloat16* __restrict__ g)
{
    extern __shared__ char dsm[];
    int tid = threadIdx.x, lane = tid & 31, wid = tid >> 5;
    int wm = wid & 1, wn = wid >> 1;
    int nt = blockIdx.x, b = blockIdx.y, o = blockIdx.z;

    const __nv_bfloat16* A = Wc + (size_t)(2 + o) * 65536;
    const __nv_bfloat16* B = xT + ((size_t)b * NNE + (size_t)nt * 128) * CIN;

    float acc[4][4][4];
    u32 sA = (u32)__cvta_generic_to_shared(dsm);
    u32 sB = sA + NSTAGE * TILE_B;
    hmma_gemm(sA, sB, A, CIN, B, CIN, CIN, tid, acc);

    const float* bias = (o == 0) ? bgav : bgah;
    __nv_bfloat16* dst = g + (size_t)(o * BB + b) * MIDC * NNE + (size_t)nt * 128;
#pragma unroll
    for (int mf = 0; mf < 4; mf++)
#pragma unroll
        for (int nf = 0; nf < 4; nf++)
#pragma unroll
            for (int h = 0; h < 2; h++) {
                int r = wm * 64 + mf * 16 + (lane >> 2) + h * 8;
                int c = wn * 32 + nf * 8 + ((lane & 3) << 1);
                float bval = bias[r];
                *reinterpret_cast<u32*>(dst + (size_t)r * NNE + c) =
                    pack_bf16(acc[mf][nf][h * 2] + bval, acc[mf][nf][h * 2 + 1] + bval);
            }
}

// ET8[sel][b][j][i] = e4m3(exp(scale*fa8[j]·fq8[i]) / 8); Z += col sums.
// FP8 single-tile GEMM (K=128 fp8). grid (it 18, jt 18, b + 8*sel).
__global__ __launch_bounds__(256, 2) void k_score(
    const unsigned char* __restrict__ ft, unsigned char* __restrict__ et,
    float* __restrict__ Z)
{
    extern __shared__ char dsm[];
    __shared__ float zs[2][128];
    int tid = threadIdx.x, lane = tid & 31, wid = tid >> 5;
    int wm = wid & 1, wn = wid >> 1;
    int it = blockIdx.x, jt = blockIdx.y;
    int z = blockIdx.z, b = z & 7, sel = z >> 3;

    const char* fa = (const char*)ft + (size_t)b * NNE * MIDC;
    const char* fq = (const char*)ft + (size_t)(1 + sel) * (size_t)BB * NNE * MIDC
                                     + (size_t)b * NNE * MIDC;
    const char* A = fa + (size_t)jt * 128 * MIDC;
    const char* B = fq + (size_t)it * 128 * MIDC;

    float acc[4][4][4];
    u32 sA = (u32)__cvta_generic_to_shared(dsm);
    u32 sB = sA + NSTAGE * TILE_B;
    qmma_gemm(sA, sB, A, MIDC, B, MIDC, MIDC, tid, acc);

#pragma unroll
    for (int mf = 0; mf < 4; mf++)
#pragma unroll
        for (int nf = 0; nf < 4; nf++)
#pragma unroll
            for (int e = 0; e < 4; e++)
                acc[mf][nf][e] = __expf(acc[mf][nf][e] * SCALE_S);

    unsigned char* dst = et + ((size_t)(sel * BB + b) * NNE + (size_t)jt * 128) * NNE
                            + (size_t)it * 128;
    const bool even = ((lane & 1) == 0);
#pragma unroll
    for (int mf = 0; mf < 4; mf++)
#pragma unroll
        for (int nf = 0; nf < 4; nf++)
#pragma unroll
            for (int h = 0; h < 2; h++) {
                int r = wm * 64 + mf * 16 + (lane >> 2) + h * 8;
                u32 mine = (u32)pack_e4m3(acc[mf][nf][h * 2] * SCALE_E,
                                          acc[mf][nf][h * 2 + 1] * SCALE_E);
                u32 other = __shfl_xor_sync(0xffffffffu, mine, 1);
                if (even) {
                    int c = wn * 32 + nf * 8 + ((lane & 3) << 1);
                    *reinterpret_cast<u32*>(dst + (size_t)r * NNE + c) =
                        mine | (other << 16);
                }
            }

#pragma unroll
    for (int nf = 0; nf < 4; nf++) {
        float s0 = 0.f, s1 = 0.f;
#pragma unroll
        for (int mf = 0; mf < 4; mf++) {
            s0 += acc[mf][nf][0] + acc[mf][nf][2];
            s1 += acc[mf][nf][1] + acc[mf][nf][3];
        }
#pragma unroll
        for (int off = 4; off < 32; off <<= 1) {
            s0 += __shfl_xor_sync(0xffffffffu, s0, off);
            s1 += __shfl_xor_sync(0xffffffffu, s1, off);
        }
        if (lane < 4) {
            int c = wn * 32 + nf * 8 + lane * 2;
            zs[wm][c] = s0;
            zs[wm][c + 1] = s1;
        }
    }
    __syncthreads();
    if (tid < 128)
        atomicAdd(&Z[(size_t)(sel * BB + b) * NNE + (size_t)it * 128 + tid],
                  zs[0][tid] + zs[1][tid]);
}

// oT[sel][b][j][m] = (1/2048) * sum_i ET8[j][i]·gn8[m][i]  — FP8 GEMM.
// grid (jt 18, 1, b+8*sel).
__global__ __launch_bounds__(256, 2) void k_ogemm(
    const unsigned char* __restrict__ et, const unsigned char* __restrict__ gn8,
    __nv_bfloat16* __restrict__ oT)
{
    extern __shared__ char dsm[];
    int tid = threadIdx.x, lane = tid & 31, wid = tid >> 5;
    int wm = wid & 1, wn = wid >> 1;
    int jt = blockIdx.x;
    int z = blockIdx.z, b = z & 7, sel = z >> 3;

    const char* A = (const char*)et + ((size_t)(sel * BB + b) * NNE + (size_t)jt * 128) * NNE;
    const char* B = (const char*)gn8 + (size_t)(sel * BB + b) * MIDC * NNE;

    float acc[4][4][4];
    u32 sA = (u32)__cvta_generic_to_shared(dsm);
    u32 sB = sA + NSTAGE * TILE_B;
    qmma_gemm(sA, sB, A, NNE, B, NNE, NNE, tid, acc);

    __nv_bfloat16* dst = oT + ((size_t)(sel * BB + b) * NNE + (size_t)jt * 128) * MIDC;
#pragma unroll
    for (int mf = 0; mf < 4; mf++)
#pragma unroll
        for (int nf = 0; nf < 4; nf++)
#pragma unroll
            for (int h = 0; h < 2; h++) {
                int r = wm * 64 + mf * 16 + (lane >> 2) + h * 8;
                int c = wn * 32 + nf * 8 + ((lane & 3) << 1);
                *reinterpret_cast<u32*>(dst + (size_t)r * MIDC + c) =
                    pack_bf16(acc[mf][nf][h * 2] * INV_OSCALE,
                              acc[mf][nf][h * 2 + 1] * INV_OSCALE);
            }
}

// out[sel][b][cout][n] = Wf·oT^T + bias + x. grid (nt 18, ct 4, b+8*sel).
__global__ __launch_bounds__(256, 2) void k_outconv(
    const __nv_bfloat16* __restrict__ Wc, const __nv_bfloat16* __restrict__ oT,
    const float* __restrict__ bfav, const float* __restrict__ bfah,
    const float* __restrict__ x,
    float* __restrict__ out_v, float* __restrict__ out_h)
{
    extern __shared__ char dsm[];
    int tid = threadIdx.x, lane = tid & 31, wid = tid >> 5;
    int wm = wid & 1, wn = wid >> 1;
    int nt = blockIdx.x, ct = blockIdx.y;
    int z = blockIdx.z, b = z & 7, sel = z >> 3;

    const __nv_bfloat16* A = Wc + (size_t)(4 + sel) * 65536 + (size_t)ct * 128 * MIDC;
    const __nv_bfloat16* B = oT + ((size_t)(sel * BB + b) * NNE + (size_t)nt * 128) * MIDC;

    float acc[4][4][4];
    u32 sA = (u32)__cvta_generic_to_shared(dsm);
    u32 sB = sA + NSTAGE * TILE_B;
    hmma_gemm(sA, sB, A, MIDC, B, MIDC, MIDC, tid, acc);

    const float* bias = (sel == 0) ? bfav : bfah;
    float* outp = (sel == 0) ? out_v : out_h;
#pragma unroll
    for (int mf = 0; mf < 4; mf++)
#pragma unroll
        for (int nf = 0; nf < 4; nf++)
#pragma unroll
            for (int h = 0; h < 2; h++) {
                int r = wm * 64 + mf * 16 + (lane >> 2) + h * 8;
                int c = wn * 32 + nf * 8 + ((lane & 3) << 1);
                int cout = ct * 128 + r;
                size_t base = ((size_t)b * CIN + cout) * NNE + (size_t)nt * 128 + c;
                float2 xv = *reinterpret_cast<const float2*>(x + base);
                float bval = bias[cout];
                *reinterpret_cast<float2*>(outp + base) =
                    make_float2(acc[mf][nf][h * 2] + bval + xv.x,
                                acc[mf][nf][h * 2 + 1] + bval + xv.y);
            }
}

// ============================================================================
extern "C" void kernel_launch(void* const* d_in, const int* in_sizes, int n_in,
                              void* d_out, int out_size)
{
    (void)in_sizes; (void)n_in; (void)out_size;

    const float* x    = (const float*)d_in[0];
    const float* x_h  = (const float*)d_in[1];
    const float* x_v  = (const float*)d_in[2];
    const float* Wa   = (const float*)d_in[3];
    const float* ba   = (const float*)d_in[4];
    const float* ga   = (const float*)d_in[5];
    const float* ta   = (const float*)d_in[6];
    const float* Wv   = (const float*)d_in[7];
    const float* bv   = (const float*)d_in[8];
    const float* gv   = (const float*)d_in[9];
    const float* tv   = (const float*)d_in[10];
    const float* Wgav = (const float*)d_in[11];
    const float* bgav = (const float*)d_in[12];
    const float* Wgah = (const float*)d_in[13];
    const float* bgah = (const float*)d_in[14];
    const float* Wfav = (const float*)d_in[15];
    const float* bfav = (const float*)d_in[16];
    const float* Wfah = (const float*)d_in[17];
    const float* bfah = (const float*)d_in[18];

    void* sp = nullptr;
    cudaGetSymbolAddress(&sp, d_scratch);
    char* base = (char*)sp;
    __nv_bfloat16* xT  = (__nv_bfloat16*)(base + XT_OFF);
    unsigned char* ft  = (unsigned char*)(base + FT_OFF);
    __nv_bfloat16* g   = (__nv_bfloat16*)(base + G_OFF);
    unsigned char* gn8 = (unsigned char*)(base + GN_OFF);
    unsigned char* et  = (unsigned char*)(base + ET_OFF);
    float*         Zp  = (float*)(base + Z_OFF);
    __nv_bfloat16* oT  = (__nv_bfloat16*)(base + OT_OFF);
    __nv_bfloat16* Wc  = (__nv_bfloat16*)(base + WC_OFF);

    float* out_h = (float*)d_out;
    float* out_v = out_h + (size_t)BB * CIN * NNE;

    static int attr_done = 0;
    if (!attr_done) {
        cudaFuncSetAttribute(k_fconv,   cudaFuncAttributeMaxDynamicSharedMemorySize, SMEM_DYN);
        cudaFuncSetAttribute(k_gconv,   cudaFuncAttributeMaxDynamicSharedMemorySize, SMEM_DYN);
        cudaFuncSetAttribute(k_score,   cudaFuncAttributeMaxDynamicSharedMemorySize, SMEM_DYN);
        cudaFuncSetAttribute(k_ogemm,   cudaFuncAttributeMaxDynamicSharedMemorySize, SMEM_DYN);
        cudaFuncSetAttribute(k_outconv, cudaFuncAttributeMaxDynamicSharedMemorySize, SMEM_DYN);
        attr_done = 1;
    }

    // prep: transpose x to bf16 [n][c]; weights to bf16; zero Z
    transpose_x<<<dim3(NNE / 32, CIN / 32, 3 * BB), 256>>>(x, x_v, x_h, xT);
    WC6 w = {{ Wa, Wv, Wgav, Wgah, Wfav, Wfah }};
    conv_weights<<<1536, 256>>>(w, Wc, Zp);

    // input convs: f -> fp8, g -> bf16
    k_fconv<<<dim3(18, BB, 3), 256, SMEM_DYN>>>(xT, Wc, ba, ga, ta, bv, gv, tv, ft);
    k_gconv<<<dim3(18, BB, 2), 256, SMEM_DYN>>>(xT, Wc, bgav, bgah, g);

    // scores: FP8 GEMM, ET8 = e4m3(exp(scale*S)/8)^T, Z = per-query sums (fp32)
    k_score<<<dim3(18, 18, 16), 256, SMEM_DYN>>>(ft, et, Zp);

    // fold 16384/Z into g -> e4m3
    gnorm<<<(2 * BB * MIDC * NNE) / 512, 256>>>(g, Zp, gn8);

    // oT = (ET8 · gn8^T) / 2048  — FP8 tensor GEMM
    k_ogemm<<<dim3(18, 1, 16), 256, SMEM_DYN>>>(et, gn8, oT);

    // output convs + residual
    k_outconv<<<dim3(18, 4, 16), 256, SMEM_DYN>>>(Wc, oT, bfav, bfah, x, out_v, out_h);
}